// round 16
// baseline (speedup 1.0000x reference)
#include <cuda_runtime.h>

static constexpr int CHW   = 3 * 128 * 128;   // 49152
static constexpr int CHW4  = CHW / 4;         // 12288 float4
static constexpr int S     = 16;
static constexpr int N     = 64;
static constexpr int NPAIR = N * S;           // 1024

// Per-(n,s) squared distance partials.
__device__ float g_partial[NPAIR];

__global__ __launch_bounds__(512)
void pair_dist_kernel(const float* __restrict__ inputs,
                      const float* __restrict__ samples) {
    const int pair = blockIdx.x;          // 0..1023
    const int n = pair >> 4;
    const int s = pair & 15;

    const float4* __restrict__ in4 =
        reinterpret_cast<const float4*>(inputs + (size_t)n * CHW);
    const float4* __restrict__ sm4 =
        reinterpret_cast<const float4*>(samples + ((size_t)n * S + s) * CHW);

    // R1-proven stream: 24 iters/thread, unroll 4.
    // inputs: default policy (L2-resident, reused 16x across blocks)
    // samples: __ldcs evict-first streaming -> don't evict input lines from L2
    float acc = 0.0f;
    #pragma unroll 4
    for (int i = threadIdx.x; i < CHW4; i += 512) {
        float4 a = in4[i];
        float4 b = __ldcs(&sm4[i]);
        float dx = b.x - a.x;
        float dy = b.y - a.y;
        float dz = b.z - a.z;
        float dw = b.w - a.w;
        acc = fmaf(dx, dx, acc);
        acc = fmaf(dy, dy, acc);
        acc = fmaf(dz, dz, acc);
        acc = fmaf(dw, dw, acc);
    }

    // Block reduction: warp shuffle then cross-warp via shared.
    __shared__ float sdata[16];
    #pragma unroll
    for (int o = 16; o > 0; o >>= 1)
        acc += __shfl_down_sync(0xffffffffu, acc, o);

    const int lane = threadIdx.x & 31;
    const int wid  = threadIdx.x >> 5;
    if (lane == 0) sdata[wid] = acc;
    __syncthreads();

    if (wid == 0) {
        acc = (lane < 16) ? sdata[lane] : 0.0f;
        #pragma unroll
        for (int o = 8; o > 0; o >>= 1)
            acc += __shfl_down_sync(0xffffffffu, acc, o);
        if (lane == 0) g_partial[pair] = acc;
    }
}

__global__ __launch_bounds__(1024)
void min_sum_kernel(float* __restrict__ out) {
    // 1024 threads: one partial each (single parallel load -> ~one mem latency).
    const int t = threadIdx.x;
    float v = g_partial[t];   // t = n*16 + s; 16-lane groups share one n

    // Butterfly min over the 16 samples (offsets 1,2,4,8 stay within the group).
    #pragma unroll
    for (int o = 1; o < 16; o <<= 1)
        v = fminf(v, __shfl_xor_sync(0xffffffffu, v, o));

    __shared__ float mins[N];
    if ((t & 15) == 0) mins[t >> 4] = v;
    __syncthreads();

    if (t == 0) {
        float total = 0.0f;
        #pragma unroll
        for (int nn = 0; nn < N; nn++)
            total += mins[nn];            // fixed order -> deterministic
        out[0] = total;
    }
}

extern "C" void kernel_launch(void* const* d_in, const int* in_sizes, int n_in,
                              void* d_out, int out_size) {
    const float* inputs  = (const float*)d_in[0];   // [64,3,128,128]
    const float* samples = (const float*)d_in[1];   // [64,16,3,128,128]
    float* out = (float*)d_out;

    pair_dist_kernel<<<NPAIR, 512>>>(inputs, samples);
    min_sum_kernel<<<1, 1024>>>(out);
}

// round 17
// speedup vs baseline: 1.0339x; 1.0339x over previous
#include <cuda_runtime.h>

static constexpr int CHW   = 3 * 128 * 128;   // 49152
static constexpr int CHW4  = CHW / 4;         // 12288 float4
static constexpr int S     = 16;
static constexpr int N     = 64;
static constexpr int NPAIR = N * S;           // 1024

__device__ float        g_partial[NPAIR];
__device__ unsigned int g_flag[NPAIR];        // zero-init; reset by owners
__device__ float        g_sum;                // zero-init; reset by last owner
__device__ unsigned int g_cnt = 0;            // wraps at N

__global__ __launch_bounds__(512)
void min_dist_kernel(const float* __restrict__ inputs,
                     const float* __restrict__ samples,
                     float* __restrict__ out) {
    const int pair = blockIdx.x;          // 0..1023
    const int n = pair >> 4;
    const int s = pair & 15;

    const float4* __restrict__ in4 =
        reinterpret_cast<const float4*>(inputs + (size_t)n * CHW);
    const float4* __restrict__ sm4 =
        reinterpret_cast<const float4*>(samples + ((size_t)n * S + s) * CHW);

    // R1-proven stream: 24 iters/thread, 2 plain float4 loads, unroll 4.
    float acc = 0.0f;
    #pragma unroll 4
    for (int i = threadIdx.x; i < CHW4; i += 512) {
        float4 a = in4[i];
        float4 b = sm4[i];
        float dx = b.x - a.x;
        float dy = b.y - a.y;
        float dz = b.z - a.z;
        float dw = b.w - a.w;
        acc = fmaf(dx, dx, acc);
        acc = fmaf(dy, dy, acc);
        acc = fmaf(dz, dz, acc);
        acc = fmaf(dw, dw, acc);
    }

    // Block reduction: warp shuffle then cross-warp via shared.
    __shared__ float sdata[16];
    #pragma unroll
    for (int o = 16; o > 0; o >>= 1)
        acc += __shfl_down_sync(0xffffffffu, acc, o);

    const int lane = threadIdx.x & 31;
    const int wid  = threadIdx.x >> 5;
    if (lane == 0) sdata[wid] = acc;
    __syncthreads();

    if (wid != 0) return;                 // only warp 0 continues

    acc = (lane < 16) ? sdata[lane] : 0.0f;
    #pragma unroll
    for (int o = 8; o > 0; o >>= 1)
        acc += __shfl_down_sync(0xffffffffu, acc, o);
    // lane 0 now holds this block's full distance; broadcast to the warp
    const float total = __shfl_sync(0xffffffffu, acc, 0);

    if (s != 15) {
        // Producer: publish partial, signal flag, exit (no extra serialization).
        if (lane == 0) {
            g_partial[pair] = total;
            __threadfence();
            atomicExch(&g_flag[pair], 1u);
        }
        return;
    }

    // ---- owner block (s == 15): gather 15 partner partials for this n ----
    const int base = n << 4;              // pair index of (n, 0)
    if (lane < 15) {
        // Poll partner flag (L2 atomic read; partners usually already done
        // since owner bids are highest -> scheduled last).
        while (atomicAdd(&g_flag[base + lane], 0u) == 0u)
            __nanosleep(64);
    }
    __syncwarp();
    __threadfence();                      // order flag read before partial read

    float m;
    if (lane < 15) {
        m = __ldcg(&g_partial[base + lane]);
        g_flag[base + lane] = 0u;         // reset for next graph replay
    } else if (lane == 15) {
        m = total;                        // own sample's distance
    } else {
        m = __int_as_float(0x7f800000);   // +inf
    }
    // Butterfly min over 16 lanes.
    #pragma unroll
    for (int o = 8; o > 0; o >>= 1)
        m = fminf(m, __shfl_down_sync(0xffffffffu, m, o));

    if (lane == 0) {
        atomicAdd(&g_sum, m);             // per-batch min into global sum
        __threadfence();
        unsigned int prev = atomicInc(&g_cnt, N - 1);   // wraps -> self-reset
        if (prev == N - 1) {
            float r = __ldcg(&g_sum);     // all 64 adds fenced-visible
            out[0] = r;
            g_sum = 0.0f;                 // reset for next replay
            __threadfence();
        }
    }
}

extern "C" void kernel_launch(void* const* d_in, const int* in_sizes, int n_in,
                              void* d_out, int out_size) {
    const float* inputs  = (const float*)d_in[0];   // [64,3,128,128]
    const float* samples = (const float*)d_in[1];   // [64,16,3,128,128]
    float* out = (float*)d_out;

    min_dist_kernel<<<NPAIR, 512>>>(inputs, samples, out);
}